// round 17
// baseline (speedup 1.0000x reference)
#include <cuda_runtime.h>
#include <cuda_fp16.h>
#include <cstdint>
#include <math.h>

#define SEQ 2048
#define NB 2
#define DM 1024
#define NH 16
#define HD 64
#define TOTROWS (NB*SEQ)
#define NBH (NB*NH)

#if defined(__CUDA_ARCH_SPECIFIC__) || defined(__CUDA_ARCH_FAMILY_SPECIFIC__) || \
    defined(__CUDA_ARCH_FEAT_SM103_ALL) || defined(__CUDA_ARCH_FEAT_SM100_ALL) || !defined(__CUDA_ARCH__)
#define HAS_TCGEN05 1
#else
#define HAS_TCGEN05 0
#endif

// ---------------------------------------------------------------------------
// Scratch (all fp16)
// ---------------------------------------------------------------------------
__device__ __half g_Xhi[TOTROWS*DM];
__device__ __half g_Xlo[TOTROWS*DM];
__device__ __half g_Wt [3*DM*DM];      // [mat][n][k]
__device__ __half g_Wo [DM*DM];
__device__ __half g_Qh [NBH*SEQ*HD];   // pre-scaled 1/8
__device__ __half g_Kh [NBH*SEQ*HD];
__device__ __half g_Vt [NBH*HD*SEQ];   // [bh][d][s]
__device__ __half g_Ct [NBH*SEQ*HD];

__device__ __forceinline__ uint32_t smem_u32(const void* p) {
    uint32_t a;
    asm("{ .reg .u64 t; cvta.to.shared.u64 t, %1; cvt.u32.u64 %0, t; }" : "=r"(a) : "l"(p));
    return a;
}
__device__ __forceinline__ void f16_split(float v, __half& h, __half& l) {
    h = __float2half_rn(v);
    l = __float2half_rn(v - __half2float(h));
}
__device__ __forceinline__ uint32_t pack2f(float a, float b) {
    __half2 h2 = __floats2half2_rn(a, b);
    return *reinterpret_cast<uint32_t*>(&h2);
}

#define CP16(dst, src) \
    asm volatile("cp.async.cg.shared.global [%0], [%1], 16;" :: "r"((uint32_t)(dst)), "l"(src) : "memory")
#define CP_COMMIT() asm volatile("cp.async.commit_group;" ::: "memory")
#define CP_WAIT(n)  asm volatile("cp.async.wait_group %0;" :: "n"(n) : "memory")

#if HAS_TCGEN05
__device__ __forceinline__ uint32_t elect_one_pred() {
    uint32_t pred;
    asm volatile("{\n\t.reg .pred p;\n\telect.sync _|p, 0xFFFFFFFF;\n\t"
                 "selp.b32 %0, 1, 0, p;\n\t}" : "=r"(pred));
    return pred;
}
#define TCGEN05_ALLOC(sa, n) \
    asm volatile("tcgen05.alloc.cta_group::1.sync.aligned.shared::cta.b32 [%0], %1;" \
        :: "r"((uint32_t)(sa)), "r"((uint32_t)(n)) : "memory")
#define TCGEN05_DEALLOC(ta, n) \
    asm volatile("tcgen05.dealloc.cta_group::1.sync.aligned.b32 %0, %1;" :: "r"(ta), "r"((uint32_t)(n)))
#define TCGEN05_RELINQ() asm volatile("tcgen05.relinquish_alloc_permit.cta_group::1.sync.aligned;")
#define TCGEN05_COMMIT(mb) \
    asm volatile("tcgen05.commit.cta_group::1.mbarrier::arrive::one.shared::cluster.b64 [%0];" \
        :: "r"((uint32_t)(mb)) : "memory")
#define TCGEN05_WAIT_LD() asm volatile("tcgen05.wait::ld.sync.aligned;" ::: "memory")
#define TCGEN05_FENCE_AFTER() asm volatile("tcgen05.fence::after_thread_sync;" ::: "memory")
#define FENCE_ASYNC_SHARED() asm volatile("fence.proxy.async.shared::cta;" ::: "memory")
#define MBARRIER_INIT(mb, c) \
    asm volatile("mbarrier.init.shared.b64 [%0], %1;" :: "r"((uint32_t)(mb)), "r"((uint32_t)(c)) : "memory")
#define MBARRIER_WAIT_PARITY(mb, par) do { \
    uint32_t _m = (uint32_t)(mb), _p = (uint32_t)(par), _d; \
    asm volatile("{\n\t.reg .pred p;\n\t" \
        "mbarrier.try_wait.parity.acquire.cta.shared::cta.b64 p, [%1], %2;\n\t" \
        "selp.b32 %0, 1, 0, p;\n\t}" : "=r"(_d) : "r"(_m), "r"(_p) : "memory"); \
    if (!_d) { \
        asm volatile("{\n\t.reg .pred P1;\n\t" \
            "WL_%=:\n\t" \
            "mbarrier.try_wait.parity.acquire.cta.shared::cta.b64 P1, [%0], %1, 0x989680;\n\t" \
            "@P1 bra.uni WD_%=;\n\tbra.uni WL_%=;\n\tWD_%=:\n\t}" :: "r"(_m), "r"(_p) : "memory"); \
    } } while(0)
#define TCGEN05_LD_X32(r, addr) \
    asm volatile("tcgen05.ld.sync.aligned.32x32b.x32.b32 " \
        "{%0, %1, %2, %3, %4, %5, %6, %7, %8, %9, %10, %11, %12, %13, %14, %15, " \
        " %16, %17, %18, %19, %20, %21, %22, %23, %24, %25, %26, %27, %28, %29, %30, %31}, [%32];" \
        : "=r"((r)[0]),"=r"((r)[1]),"=r"((r)[2]),"=r"((r)[3]),"=r"((r)[4]),"=r"((r)[5]), \
          "=r"((r)[6]),"=r"((r)[7]),"=r"((r)[8]),"=r"((r)[9]),"=r"((r)[10]),"=r"((r)[11]), \
          "=r"((r)[12]),"=r"((r)[13]),"=r"((r)[14]),"=r"((r)[15]),"=r"((r)[16]),"=r"((r)[17]), \
          "=r"((r)[18]),"=r"((r)[19]),"=r"((r)[20]),"=r"((r)[21]),"=r"((r)[22]),"=r"((r)[23]), \
          "=r"((r)[24]),"=r"((r)[25]),"=r"((r)[26]),"=r"((r)[27]),"=r"((r)[28]),"=r"((r)[29]), \
          "=r"((r)[30]),"=r"((r)[31]) : "r"(addr))

static constexpr uint64_t DESC_SW128 =
    (uint64_t(2) << 61) | (uint64_t(1) << 46) | (uint64_t(64) << 32) | (uint64_t(1) << 16);
__device__ __forceinline__ uint64_t make_desc(uint32_t a) { return DESC_SW128 | ((uint64_t)(a >> 4) & 0x3FFF); }
#define GIDESC    ((8u<<24)|(32u<<17)|(1u<<4))   // M=128 N=256 fp16
#define QKIDESC   ((8u<<24)|(16u<<17)|(1u<<4))   // M=128 N=128 fp16
#define PVIDESC   ((8u<<24)|( 8u<<17)|(1u<<4))   // M=128 N=64  fp16

__device__ __forceinline__ void mma16(uint32_t d, uint64_t ad, uint64_t bd, uint32_t idesc, uint32_t en) {
    asm volatile("{\n\t.reg .pred p;\n\tsetp.ne.u32 p, %5, 0;\n\t"
        "tcgen05.mma.cta_group::1.kind::f16 [%0], %1, %2, %3, {%4,%4,%4,%4}, p;\n\t}"
        :: "r"(d), "l"(ad), "l"(bd), "r"(idesc), "r"(0u), "r"(en) : "memory");
}
#endif

// ---------------- prep ----------------
__global__ __launch_bounds__(256) void split_x_kernel(const float* __restrict__ src) {
    int i = blockIdx.x*256 + threadIdx.x;
    float4 v = ((const float4*)src)[i];
    float f[4] = {v.x, v.y, v.z, v.w};
    #pragma unroll
    for (int j = 0; j < 4; j++) { __half h, l; f16_split(f[j], h, l); g_Xhi[i*4+j] = h; g_Xlo[i*4+j] = l; }
}
__global__ __launch_bounds__(256) void split_wo_kernel(const float* __restrict__ src) {
    int i = blockIdx.x*256 + threadIdx.x;
    float4 v = ((const float4*)src)[i];
    g_Wo[i*4+0] = __float2half_rn(v.x);
    g_Wo[i*4+1] = __float2half_rn(v.y);
    g_Wo[i*4+2] = __float2half_rn(v.z);
    g_Wo[i*4+3] = __float2half_rn(v.w);
}
__global__ __launch_bounds__(1024) void transw_kernel(
    const float* __restrict__ Wq, const float* __restrict__ Wk, const float* __restrict__ Wv)
{
    __shared__ float T[32][33];
    const int mat = blockIdx.z, h = blockIdx.y >> 1, n0 = (blockIdx.y & 1)*32, k0 = blockIdx.x*32;
    const int tx = threadIdx.x, ty = threadIdx.y;
    const float* W = (mat == 0) ? Wq : (mat == 1) ? Wk : Wv;
    T[ty][tx] = W[((size_t)h*DM + k0 + ty)*HD + n0 + tx];
    __syncthreads();
    size_t di = (size_t)mat*DM*DM + (size_t)(h*HD + n0 + ty)*DM + k0 + tx;
    g_Wt[di] = __float2half_rn(T[tx][ty]);
}

// ---------------------------------------------------------------------------
// GEMM: proven double-buffer flow. mode0: Mt=256 (2 subtiles share B stage),
// (Ahi+Alo)xB; mode1: Mt=128, AxB.
// Stage 96KB: Ah0 @0, Ah1 @16K, Al0 @32K, Al1 @48K, B @64K (32K).
// ---------------------------------------------------------------------------
#define STG 98304
#define GEMM_SMEM (1024 + 2*STG)   // 197632

__global__ __launch_bounds__(256, 1)
void gemm_kernel(int mode, const float* __restrict__ bq, const float* __restrict__ bk,
                 const float* __restrict__ bv, const float* __restrict__ bo,
                 float* __restrict__ outflat)
{
    extern __shared__ char smem[];
    const int tid = threadIdx.x;
    const int mt = (mode == 0) ? 2 : 1;
    const int m0 = blockIdx.x * 128 * mt;

    const __half *Ah, *Al, *B;
    int mat = 0, nt;
    if (mode == 0) {
        mat = blockIdx.y >> 2; nt = blockIdx.y & 3;
        Ah = g_Xhi; Al = g_Xlo;
        B = g_Wt + (size_t)mat*DM*DM;
    } else {
        nt = blockIdx.y;
        Ah = g_Ct; Al = g_Ct; B = g_Wo;
    }
    const int n0 = nt * 256;

#if HAS_TCGEN05
    const uint32_t sb = smem_u32(smem);
    const int wid = tid >> 5, lid = tid & 31;

    if (wid == 0) { TCGEN05_ALLOC(sb, 512); TCGEN05_RELINQ(); }
    if (tid == 0) { MBARRIER_INIT(sb + 16, 1); MBARRIER_INIT(sb + 24, 1); }
    __syncthreads();
    uint32_t tmem;
    asm volatile("ld.shared.b32 %0, [%1];" : "=r"(tmem) : "r"(sb));

    auto stage_chunk = [&](int c, int s) {
        const uint32_t ba = sb + 1024 + s*STG;
        const int col0 = c * 64;
        for (int g = tid; g < (mt << 10); g += 256) {      // A: 128*mt rows x 128B
            int r = g >> 3, q = g & 7;
            int sub = r >> 7, rr = r & 127;
            int m = m0 + r;
            size_t go;
            if (mode == 0) go = (size_t)m*DM + col0 + q*8;
            else           go = (((size_t)(m >> 11)*NH + c)*SEQ + (m & 2047))*HD + q*8;
            uint32_t off = (uint32_t)(rr*128 + q*16); off ^= (off >> 3) & 0x70;
            CP16(ba + sub*16384 + off, Ah + go);
            if (mode == 0) CP16(ba + 32768 + sub*16384 + off, Al + go);
        }
        #pragma unroll
        for (int g = tid; g < 2048; g += 256) {            // B: 256 rows x 128B
            int r = g >> 3, q = g & 7;
            size_t go = (size_t)(n0 + r)*DM + col0 + q*8;
            uint32_t off = (uint32_t)(r*128 + q*16); off ^= (off >> 3) & 0x70;
            CP16(ba + 65536 + off, B + go);
        }
    };

    stage_chunk(0, 0); CP_COMMIT();
    stage_chunk(1, 1); CP_COMMIT();
    int phase[2] = {0, 0};
    for (int c = 0; c < 16; c++) {
        const int s = c & 1;
        if (c < 15) { CP_WAIT(1); } else { CP_WAIT(0); }
        FENCE_ASYNC_SHARED();
        __syncthreads();
        if (wid == 0 && elect_one_pred()) {
            uint32_t b = sb + 1024 + s*STG;
            uint64_t dB = make_desc(b + 65536);
            for (int sub = 0; sub < mt; sub++) {
                uint32_t dacc = tmem + sub*256;
                uint64_t dAh = make_desc(b + sub*16384);
                uint64_t dAl = make_desc(b + 32768 + sub*16384);
                #pragma unroll
                for (int k = 0; k < 4; k++)
                    mma16(dacc, dAh + k*2, dB + k*2, GIDESC, (c == 0 && k == 0) ? 0u : 1u);
                if (mode == 0) {
                    #pragma unroll
                    for (int k = 0; k < 4; k++) mma16(dacc, dAl + k*2, dB + k*2, GIDESC, 1u);
                }
            }
            TCGEN05_COMMIT(sb + 16 + s*8);
        }
        MBARRIER_WAIT_PARITY(sb + 16 + s*8, phase[s]);
        phase[s] ^= 1;
        if (c + 2 < 16) { stage_chunk(c + 2, s); CP_COMMIT(); }
    }
    TCGEN05_FENCE_AFTER();
    __syncthreads();

    // ---- epilogue per subtile ----
    for (int sub = 0; sub < mt; sub++) {
        const uint32_t tm = tmem + sub*256;
        const int m0s = m0 + sub*128;
        const int wg = wid >> 2;
        const int srow = (wid & 3)*32 + lid;
        float* Smine = (float*)(smem + 1024 + wg*17024);
        for (int nb = 0; nb < 4; nb++) {
            uint32_t r[32];
            TCGEN05_LD_X32(r, tm + wg*128 + nb*32);
            TCGEN05_WAIT_LD();
            #pragma unroll
            for (int c2 = 0; c2 < 32; c2++) Smine[srow*33 + c2] = __uint_as_float(r[c2]);
            __syncthreads();
            if (mode == 0 && mat == 2) {
                const int colg = tid & 63, seg = tid >> 6;
                const int half = colg >> 5, cc = colg & 31;
                const float* Sc = (const float*)(smem + 1024 + half*17024);
                const int gc = n0 + half*128 + nb*32 + cc;
                const int h = gc >> 6, d = gc & 63;
                const int b = m0s >> 11;
                const int sq0 = (m0s & 2047) + seg*32;
                const float bias = bv[gc];
                uint32_t hp[16];
                #pragma unroll
                for (int jj = 0; jj < 16; jj++)
                    hp[jj] = pack2f(Sc[(seg*32 + 2*jj + 0)*33 + cc] + bias,
                                    Sc[(seg*32 + 2*jj + 1)*33 + cc] + bias);
                size_t ad = ((size_t)(b*NH + h)*HD + d)*SEQ + sq0;
                #pragma unroll
                for (int q = 0; q < 4; q++)
                    *(uint4*)(g_Vt + ad + q*8) = *(uint4*)&hp[q*4];
            } else {
                const int wg2 = tid >> 7, rr = tid & 127;
                const float* Sr = (const float*)(smem + 1024 + wg2*17024) + rr*33;
                const int gc0 = n0 + wg2*128 + nb*32;
                const int m = m0s + rr;
                if (mode == 0) {
                    const float* bias = ((mat == 0) ? bq : bk) + gc0;
                    const int h = gc0 >> 6, d0 = gc0 & 63;
                    const int b = m >> 11, sq = m & 2047;
                    __half* dst = (mat == 0) ? g_Qh : g_Kh;
                    const float scale = (mat == 0) ? 0.125f : 1.0f;
                    size_t ad = ((size_t)(b*NH + h)*SEQ + sq)*HD + d0;
                    uint32_t hp[16];
                    #pragma unroll
                    for (int jj = 0; jj < 16; jj++)
                        hp[jj] = pack2f((Sr[2*jj] + bias[2*jj])*scale, (Sr[2*jj+1] + bias[2*jj+1])*scale);
                    #pragma unroll
                    for (int q = 0; q < 4; q++) *(uint4*)(dst + ad + q*8) = *(uint4*)&hp[q*4];
                } else {
                    const float* bias = bo + gc0;
                    float* gbase = outflat + (size_t)m*DM + gc0;
                    #pragma unroll
                    for (int j = 0; j < 32; j += 4) {
                        float4 v;
                        v.x = Sr[j+0] + bias[j+0]; v.y = Sr[j+1] + bias[j+1];
                        v.z = Sr[j+2] + bias[j+2]; v.w = Sr[j+3] + bias[j+3];
                        *(float4*)(gbase + j) = v;
                    }
                }
            }
            __syncthreads();
        }
    }
    if (wid == 0) TCGEN05_DEALLOC(tmem, 512);
#else
    for (int idx = tid; idx < 128*mt*256; idx += 256) {
        int i = idx >> 8, j = idx & 255;
        int m = m0 + i, gc = n0 + j;
        float acc = 0.f;
        for (int k = 0; k < DM; k++) {
            size_t ga;
            if (mode == 0) ga = (size_t)m*DM + k;
            else ga = (((size_t)(m >> 11)*NH + (k >> 6))*SEQ + (m & 2047))*HD + (k & 63);
            float a = (mode == 0) ? (__half2float(Ah[ga]) + __half2float(Al[ga]))
                                  : __half2float(Ah[ga]);
            acc += a * __half2float(B[(size_t)gc*DM + k]);
        }
        if (mode == 0) {
            const float* barr = (mat == 0) ? bq : (mat == 1) ? bk : bv;
            int h = gc >> 6, d0 = gc & 63, b = m >> 11, sq = m & 2047, bhid = b*NH + h;
            float val = (acc + barr[gc]) * ((mat == 0) ? 0.125f : 1.0f);
            if (mat == 0) g_Qh[((size_t)bhid*SEQ+sq)*HD+d0] = __float2half_rn(val);
            else if (mat == 1) g_Kh[((size_t)bhid*SEQ+sq)*HD+d0] = __float2half_rn(val);
            else g_Vt[((size_t)bhid*HD+d0)*SEQ+sq] = __float2half_rn(val);
        } else outflat[(size_t)m*DM + gc] = acc + bo[gc];
    }
#endif
}

// ---------------------------------------------------------------------------
// attention: R16, unchanged. 2 q-subtiles, 512 threads, single-fp16 V/Ctx.
// ---------------------------------------------------------------------------
#define AQ(s) ((s)*16384)
#define AK(b) (32768 + (b)*16384)
#define AV(b) (65536 + (b)*16384)
#define AP(s) (98304 + (s)*32768)
#define ATTN_SMEM (1024 + 163840)

__global__ __launch_bounds__(512, 1)
void attn_kernel()
{
    extern __shared__ char smem[];
    const int tid = threadIdx.x, qt = blockIdx.x, bh = blockIdx.y;

#if HAS_TCGEN05
    const uint32_t sb = smem_u32(smem);
    const uint32_t ba = sb + 1024;
    char* base = smem + 1024;
    const int wid = tid >> 5, lane = tid & 31;
    const size_t qkb = (size_t)bh*SEQ*HD;
    const size_t vtb = (size_t)bh*HD*SEQ;

    if (wid == 0) { TCGEN05_ALLOC(sb, 512); TCGEN05_RELINQ(); }
    if (tid == 0) { MBARRIER_INIT(sb + 16, 1); MBARRIER_INIT(sb + 24, 1); }
    __syncthreads();
    uint32_t tmem;
    asm volatile("ld.shared.b32 %0, [%1];" : "=r"(tmem) : "r"(sb));
    const uint32_t tmS0 = tmem,       tmS1 = tmem + 128;
    const uint32_t tmO0 = tmem + 256, tmO1 = tmem + 320;

    auto stageK = [&](int kt, int b) {
        #pragma unroll
        for (int g = tid; g < 1024; g += 512) {
            int r = g >> 3, q = g & 7;
            size_t go = qkb + (size_t)(kt*128 + r)*HD + q*8;
            uint32_t off = (uint32_t)(r*128 + q*16); off ^= (off >> 3) & 0x70;
            CP16(ba + AK(b) + off, g_Kh + go);
        }
    };
    auto stageV = [&](int kt, int b) {
        #pragma unroll
        for (int g = tid; g < 1024; g += 512) {
            int blk = g >> 9, rem = g & 511;
            int d = rem >> 3, sc = rem & 7;
            size_t go = vtb + (size_t)d*SEQ + kt*128 + blk*64 + sc*8;
            uint32_t off = (uint32_t)(blk*8192 + d*128 + sc*16); off ^= (off >> 3) & 0x70;
            CP16(ba + AV(b) + off, g_Vt + go);
        }
    };

    #pragma unroll
    for (int g = tid; g < 2048; g += 512) {
        int r = g >> 3, q = g & 7;
        int sub = r >> 7, rr = r & 127;
        size_t go = qkb + (size_t)(qt*256 + r)*HD + q*8;
        uint32_t off = (uint32_t)(rr*128 + q*16); off ^= (off >> 3) & 0x70;
        CP16(ba + AQ(sub) + off, g_Qh + go);
    }
    stageK(0, 0); stageV(0, 0); CP_COMMIT();
    stageK(1, 1); CP_COMMIT();
    CP_WAIT(1);
    FENCE_ASYNC_SHARED();
    __syncthreads();

    auto issueQKpair = [&](int kb) {
        uint64_t dQ0 = make_desc(ba + AQ(0));
        uint64_t dQ1 = make_desc(ba + AQ(1));
        uint64_t dK  = make_desc(ba + AK(kb));
        #pragma unroll
        for (int k = 0; k < 4; k++) mma16(tmS0, dQ0 + k*2, dK + k*2, QKIDESC, k ? 1u : 0u);
        #pragma unroll
        for (int k = 0; k < 4; k++) mma16(tmS1, dQ1 + k*2, dK + k*2, QKIDESC, k ? 1u : 0u);
        TCGEN05_COMMIT(sb + 16);
    };
    auto issuePVpair = [&](int vb, int first) {
        uint64_t dV = make_desc(ba + AV(vb));
        #pragma unroll
        for (int s2 = 0; s2 < 2; s2++) {
            uint64_t dP = make_desc(ba + AP(s2));
            uint32_t dst = s2 ? tmO1 : tmO0;
            #pragma unroll
            for (int c = 0; c < 8; c++)
                mma16(dst, dP + (c >> 2)*1024 + (c & 3)*2, dV + (c >> 2)*512 + (c & 3)*2,
                      PVIDESC, (first && c == 0) ? 0u : 1u);
        }
        TCGEN05_COMMIT(sb + 24);
    };

    if (wid == 0 && elect_one_pred()) issueQKpair(0);

    const int sub  = wid >> 3;
    const int pblk = (wid >> 2) & 1;
    const int rq   = (wid & 3)*32 + lane;
    const uint32_t tmS = sub ? tmS1 : tmS0;
    const int chalf = pblk*64;
    float lpart = 0.f;
    int ph0 = 0, ph1 = 0;

    for (int kt = 0; kt < 16; kt++) {
        MBARRIER_WAIT_PARITY(sb + 16, ph0); ph0 ^= 1;
        TCGEN05_FENCE_AFTER();
        if (kt + 2 < 16) stageK(kt + 2, kt & 1);
        uint32_t pk[32];
        float ls = 0.f;
        {
            uint32_t r0[32], r1[32];
            TCGEN05_LD_X32(r0, tmS + chalf);
            TCGEN05_LD_X32(r1, tmS + chalf + 32);
            TCGEN05_WAIT_LD();
            #pragma unroll
            for (int i = 0; i < 16; i++) {
                float p0 = __expf(__uint_as_float(r0[2*i])), p1 = __expf(__uint_as_float(r0[2*i+1]));
                ls += p0 + p1; pk[i] = pack2f(p0, p1);
            }
            #pragma unroll
            for (int i = 0; i < 16; i++) {
                float p0 = __expf(__uint_as_float(r1[2*i])), p1 = __expf(__uint_as_float(r1[2*i+1]));
                ls += p0 + p1; pk[16 + i] = pack2f(p0, p1);
            }
        }
        lpart += ls;
        __syncthreads();
        if (kt + 1 < 16) {
            CP_WAIT(0);
            FENCE_ASYNC_SHARED();
            __syncthreads();
            if (wid == 0 && elect_one_pred()) issueQKpair((kt + 1) & 1);
        }
        if (kt > 0) { MBARRIER_WAIT_PARITY(sb + 24, ph1); ph1 ^= 1; }
        if (kt + 1 < 16) stageV(kt + 1, (kt + 1) & 1);
        CP_COMMIT();
        #pragma unroll
        for (int j = 0; j < 8; j++) {
            uint32_t off = (uint32_t)(pblk*16384 + rq*128 + j*16);
            off ^= (off >> 3) & 0x70;
            *(uint4*)(base + AP(sub) + off) = make_uint4(pk[j*4], pk[j*4+1], pk[j*4+2], pk[j*4+3]);
        }
        if (kt == 15) { CP_WAIT(0); }
        FENCE_ASYNC_SHARED();
        __syncthreads();
        if (wid == 0 && elect_one_pred()) issuePVpair(kt & 1, kt == 0);
    }
    MBARRIER_WAIT_PARITY(sb + 24, ph1);
    TCGEN05_FENCE_AFTER();

    float* lsum = (float*)(base + AP(0));
    lsum[sub*256 + pblk*128 + rq] = lpart;
    __syncthreads();
    const float linv = 1.0f / (lsum[sub*256 + rq] + lsum[sub*256 + 128 + rq]);

    uint32_t ro[32];
    TCGEN05_LD_X32(ro, (sub ? tmO1 : tmO0) + pblk*32);
    TCGEN05_WAIT_LD();
    size_t ob = ((size_t)bh*SEQ + qt*256 + sub*128 + rq)*HD + pblk*32;
    uint32_t hp[16];
    #pragma unroll
    for (int jj = 0; jj < 16; jj++)
        hp[jj] = pack2f(__uint_as_float(ro[2*jj])*linv, __uint_as_float(ro[2*jj+1])*linv);
    #pragma unroll
    for (int q = 0; q < 4; q++)
        *(uint4*)(g_Ct + ob + q*8) = *(uint4*)&hp[q*4];
    __syncthreads();
    if (wid == 0) TCGEN05_DEALLOC(tmem, 512);
#else
    for (int sub = 0; sub < 2; sub++) {
        const int q = qt*256 + sub*128 + (tid >> 2);
        const int dh = (tid & 3)*16;
        const size_t qkb = (size_t)bh*SEQ*HD, vtb = (size_t)bh*HD*SEQ;
        float qv[HD];
        for (int d = 0; d < HD; d++) qv[d] = __half2float(g_Qh[qkb + (size_t)q*HD + d]);
        float l = 0.f, o[16];
        for (int d = 0; d < 16; d++) o[d] = 0.f;
        for (int k = 0; k < SEQ; k++) {
            float s = 0.f;
            for (int d = 0; d < HD; d++) s += qv[d]*__half2float(g_Kh[qkb + (size_t)k*HD + d]);
            float p = __expf(s);
            l += p;
            for (int d = 0; d < 16; d++)
                o[d] += p*__half2float(g_Vt[vtb + (size_t)(dh+d)*SEQ + k]);
        }
        for (int d = 0; d < 16; d++)
            g_Ct[((size_t)bh*SEQ + q)*HD + dh + d] = __float2half_rn(o[d]/l);
    }
#endif
}

// ---------------------------------------------------------------------------
extern "C" void kernel_launch(void* const* d_in, const int* in_sizes, int n_in,
                              void* d_out, int out_size)
{
    const float* x  = (const float*)d_in[0];
    const float* Wq = (const float*)d_in[1];
    const float* bq = (const float*)d_in[2];
    const float* Wk = (const float*)d_in[3];
    const float* bk = (const float*)d_in[4];
    const float* Wv = (const float*)d_in[5];
    const float* bv = (const float*)d_in[6];
    const float* Wo = (const float*)d_in[7];
    const float* bo = (const float*)d_in[8];
    float* out = (float*)d_out;

    cudaFuncSetAttribute(gemm_kernel, cudaFuncAttributeMaxDynamicSharedMemorySize, GEMM_SMEM);
    cudaFuncSetAttribute(attn_kernel, cudaFuncAttributeMaxDynamicSharedMemorySize, ATTN_SMEM);

    split_x_kernel <<<(TOTROWS*DM/4)/256, 256>>>(x);
    split_wo_kernel<<<(DM*DM/4)/256, 256>>>(Wo);
    transw_kernel  <<<dim3(32, 32, 3), dim3(32, 32)>>>(Wq, Wk, Wv);

    gemm_kernel<<<dim3(16, 12), 256, GEMM_SMEM>>>(0, bq, bk, bv, bo, out);
    attn_kernel<<<dim3(8, NBH), 512, ATTN_SMEM>>>();
    gemm_kernel<<<dim3(32, 4), 256, GEMM_SMEM>>>(1, bq, bk, bv, bo, out);
}